// round 1
// baseline (speedup 1.0000x reference)
#include <cuda_runtime.h>
#include <cuda_bf16.h>

// Problem constants
#define T_DIM 1024
#define B_DIM 128
#define C_DIM 256
#define L_DIM 64
#define S_DIM 129           // 2*L+1
#define BC    (B_DIM * C_DIM)
#define NEGV  (-1e30f)

#define N_ENT_BLOCKS 1024
#define THREADS 256

// Deterministic two-stage reduction scratch (fully overwritten every call)
__device__ float g_ent_part[N_ENT_BLOCKS];
__device__ float g_ctc_part[B_DIM];

__global__ void __launch_bounds__(THREADS)
fused_ctc_entropy(const float* __restrict__ lp,
                  const int* __restrict__ targets,
                  const int* __restrict__ in_len,
                  const int* __restrict__ tgt_len)
{
    if (blockIdx.x < B_DIM) {
        // ================= CTC DP block: one batch element =================
        const int b = blockIdx.x;
        const int s = threadIdx.x;          // state index; active for s < S_DIM

        __shared__ float buf[2][S_DIM + 2]; // [pad2 | states]
        __shared__ float cap[2];            // alpha at end states, captured at t = Tlen-1

        // init pads for both buffers
        if (threadIdx.x < 2) {
            buf[0][threadIdx.x] = NEGV;
            buf[1][threadIdx.x] = NEGV;
        }

        // Per-state label and skip-transition permission
        int   label  = 0;
        bool  allow2 = false;
        if (s < S_DIM) {
            if (s & 1) {
                label = targets[b * L_DIM + (s >> 1)];
                if (s == 1) allow2 = true;
                else        allow2 = (label != targets[b * L_DIM + (s >> 1) - 1]);
            }
        }

        const int Tlen  = in_len[b];
        const int tl    = tgt_len[b];
        const int s_e1  = 2 * tl;
        const int s_e0  = 2 * tl - 1;
        const int base  = b * C_DIM + label;   // column for this state's label

        // t = 0 init
        float a = NEGV;
        if (s < S_DIM && s <= 1) a = lp[base];

        // prefetch t = 1
        float nxt = NEGV;
        if (s < S_DIM) nxt = lp[BC + base];

        __syncthreads();  // pads visible

        int p = 0;
        #pragma unroll 4
        for (int t = 1; t < T_DIM; ++t) {
            if (s < S_DIM) buf[p][2 + s] = a;
            __syncthreads();

            float curlp = nxt;
            if (s < S_DIM) {
                // prefetch next timestep's gather (off critical path)
                if (t + 1 < T_DIM) nxt = lp[(t + 1) * BC + base];

                float p1 = buf[p][1 + s];
                float p2 = allow2 ? buf[p][s] : NEGV;
                float m  = fmaxf(a, fmaxf(p1, p2));
                float l  = m + __logf(__expf(a - m) + __expf(p1 - m) + __expf(p2 - m));
                a = l + curlp;

                if (t == Tlen - 1) {
                    if (s == s_e1) cap[0] = a;
                    if (s == s_e0) cap[1] = a;
                }
            }
            p ^= 1;
        }
        __syncthreads();

        if (s == 0) {
            float a1 = cap[0], a0 = cap[1];
            float m  = fmaxf(a1, a0);
            float ll = m + __logf(__expf(a1 - m) + __expf(a0 - m));
            float nll = -ll;
            if (nll > 1e29f) nll = 0.0f;    // zero_infinity
            g_ctc_part[b] = nll;
        }
    } else {
        // ================= Entropy block: sum exp(lp)*lp =================
        const int eb  = blockIdx.x - B_DIM;
        const int tid = threadIdx.x;
        const float4* v = (const float4*)lp;
        const int n4 = (T_DIM * B_DIM * C_DIM) / 4;   // 8388608

        float acc = 0.0f;
        for (int i = eb * THREADS + tid; i < n4; i += N_ENT_BLOCKS * THREADS) {
            float4 x = v[i];
            acc += __expf(x.x) * x.x;
            acc += __expf(x.y) * x.y;
            acc += __expf(x.z) * x.z;
            acc += __expf(x.w) * x.w;
        }

        // block reduction
        __shared__ float red[THREADS / 32];
        #pragma unroll
        for (int o = 16; o > 0; o >>= 1)
            acc += __shfl_down_sync(0xFFFFFFFFu, acc, o);
        if ((tid & 31) == 0) red[tid >> 5] = acc;
        __syncthreads();
        if (tid < THREADS / 32) {
            float r = red[tid];
            #pragma unroll
            for (int o = (THREADS / 64); o > 0; o >>= 1)
                r += __shfl_down_sync(0xFFFFFFFFu, r, o);
            if (tid == 0) g_ent_part[eb] = r;
        }
    }
}

__global__ void __launch_bounds__(256)
finalize_kernel(float* __restrict__ out)
{
    const int tid = threadIdx.x;
    float acc = 0.0f;
    for (int i = tid; i < N_ENT_BLOCKS; i += 256) acc += g_ent_part[i];

    float cacc = 0.0f;
    if (tid < B_DIM) cacc = g_ctc_part[tid];

    __shared__ float red[8], redc[8];
    float a = acc, c = cacc;
    #pragma unroll
    for (int o = 16; o > 0; o >>= 1) {
        a += __shfl_down_sync(0xFFFFFFFFu, a, o);
        c += __shfl_down_sync(0xFFFFFFFFu, c, o);
    }
    if ((tid & 31) == 0) { red[tid >> 5] = a; redc[tid >> 5] = c; }
    __syncthreads();
    if (tid == 0) {
        float es = 0.0f, cs = 0.0f;
        #pragma unroll
        for (int i = 0; i < 8; ++i) { es += red[i]; cs += redc[i]; }
        // smooth_loss = mean over (T,B) of sum_c exp(lp)*lp
        float smooth = es / (float)(T_DIM * B_DIM);
        float ctc_mean = cs / (float)B_DIM;
        out[0] = 0.9f * ctc_mean + 0.1f * smooth;
    }
}

extern "C" void kernel_launch(void* const* d_in, const int* in_sizes, int n_in,
                              void* d_out, int out_size)
{
    const float* lp      = (const float*)d_in[0];
    const int*   targets = (const int*)d_in[1];
    const int*   in_len  = (const int*)d_in[2];
    const int*   tgt_len = (const int*)d_in[3];
    float*       out     = (float*)d_out;

    fused_ctc_entropy<<<B_DIM + N_ENT_BLOCKS, THREADS>>>(lp, targets, in_len, tgt_len);
    finalize_kernel<<<1, 256>>>(out);
}

// round 3
// speedup vs baseline: 1.4058x; 1.4058x over previous
#include <cuda_runtime.h>
#include <cuda_bf16.h>

// Problem constants
#define T_DIM 1024
#define B_DIM 128
#define C_DIM 256
#define L_DIM 64
#define S_DIM 129           // 2*L+1
#define BC    (B_DIM * C_DIM)
#define NEGV  (-1e30f)

#define PD 8                // prefetch ring depth
#define N_ENT_BLOCKS 1024
#define THREADS 256

// Deterministic two-stage reduction scratch (fully overwritten every call)
__device__ float g_ent_part[N_ENT_BLOCKS];
__device__ float g_ctc_part[B_DIM];

__global__ void __launch_bounds__(THREADS)
fused_ctc_entropy(const float* __restrict__ lp,
                  const int* __restrict__ targets,
                  const int* __restrict__ in_len,
                  const int* __restrict__ tgt_len)
{
    const int tid = threadIdx.x;

    if (blockIdx.x < B_DIM) {
        // ================= CTC DP block: one batch element =================
        const int b = blockIdx.x;
        const int s = tid;                   // state index; active for s < S_DIM

        __shared__ float buf[2][S_DIM + 2];  // [pad2 | states], double buffered
        __shared__ float cap[2];

        if (tid < 2) { buf[0][tid] = NEGV; buf[1][tid] = NEGV; }

        int  label  = 0;
        bool allow2 = false;
        if (s < S_DIM && (s & 1)) {
            label  = targets[b * L_DIM + (s >> 1)];
            allow2 = (s == 1) || (label != targets[b * L_DIM + (s >> 1) - 1]);
        }

        const int Tlen = in_len[b];          // in [T/2, T]
        const int tl   = tgt_len[b];
        const float* gp = lp + b * C_DIM + label;   // fixed column, stride BC over t

        // t = 0 init
        float a = NEGV;
        if (s <= 1) a = gp[0];

        // Deep prefetch ring: at loop entry for step t, ring[0] == lp[t]
        float ring[PD];
        #pragma unroll
        for (int j = 0; j < PD; ++j)
            ring[j] = (s < S_DIM) ? gp[(1 + j) * BC] : NEGV;   // 1+j <= PD < T

        __syncthreads();   // pads visible

        int p = 0;
        for (int t = 1; t < Tlen; ++t) {
            if (s < S_DIM) buf[p][2 + s] = a;
            __syncthreads();

            const float curlp = ring[0];
            #pragma unroll
            for (int j = 0; j < PD - 1; ++j) ring[j] = ring[j + 1];
            {
                int tpre = t + PD;
                if (tpre > T_DIM - 1) tpre = T_DIM - 1;
                if (s < S_DIM) ring[PD - 1] = gp[tpre * BC];
            }

            if (s < S_DIM) {
                float p1 = buf[p][1 + s];
                float p2 = allow2 ? buf[p][s] : NEGV;
                float m  = fmaxf(a, fmaxf(p1, p2));
                a = m + __logf(__expf(a - m) + __expf(p1 - m) + __expf(p2 - m)) + curlp;
            }
            p ^= 1;
        }

        // a now holds alpha at t = Tlen-1; capture end states
        if (s == 2 * tl)     cap[0] = a;
        if (s == 2 * tl - 1) cap[1] = a;
        __syncthreads();

        if (s == 0) {
            float a1 = cap[0], a0 = cap[1];
            float m  = fmaxf(a1, a0);
            float ll = m + __logf(__expf(a1 - m) + __expf(a0 - m));
            float nll = -ll;
            g_ctc_part[b] = (nll > 1e29f) ? 0.0f : nll;   // zero_infinity
        }
    } else {
        // ================= Entropy block: sum exp(lp)*lp =================
        const int eb = blockIdx.x - B_DIM;
        const float4* v = (const float4*)lp;
        const int n4 = (T_DIM * B_DIM * C_DIM) / 4;

        float acc = 0.0f;
        for (int i = eb * THREADS + tid; i < n4; i += N_ENT_BLOCKS * THREADS) {
            float4 x = v[i];
            acc += __expf(x.x) * x.x;
            acc += __expf(x.y) * x.y;
            acc += __expf(x.z) * x.z;
            acc += __expf(x.w) * x.w;
        }

        __shared__ float red[THREADS / 32];
        #pragma unroll
        for (int o = 16; o > 0; o >>= 1)
            acc += __shfl_down_sync(0xFFFFFFFFu, acc, o);
        if ((tid & 31) == 0) red[tid >> 5] = acc;
        __syncthreads();
        if (tid < THREADS / 32) {
            float r = red[tid];
            #pragma unroll
            for (int o = (THREADS / 64); o > 0; o >>= 1)
                r += __shfl_down_sync(0xFFFFFFFFu, r, o);
            if (tid == 0) g_ent_part[eb] = r;
        }
    }
}

__global__ void __launch_bounds__(256)
finalize_kernel(float* __restrict__ out)
{
    const int tid = threadIdx.x;
    float acc = 0.0f;
    for (int i = tid; i < N_ENT_BLOCKS; i += 256) acc += g_ent_part[i];

    float c = (tid < B_DIM) ? g_ctc_part[tid] : 0.0f;

    __shared__ float red[8], redc[8];
    #pragma unroll
    for (int o = 16; o > 0; o >>= 1) {
        acc += __shfl_down_sync(0xFFFFFFFFu, acc, o);
        c   += __shfl_down_sync(0xFFFFFFFFu, c, o);
    }
    if ((tid & 31) == 0) { red[tid >> 5] = acc; redc[tid >> 5] = c; }
    __syncthreads();
    if (tid == 0) {
        float es = 0.0f, cs = 0.0f;
        #pragma unroll
        for (int i = 0; i < 8; ++i) { es += red[i]; cs += redc[i]; }
        float smooth   = es / (float)(T_DIM * B_DIM);
        float ctc_mean = cs / (float)B_DIM;
        out[0] = 0.9f * ctc_mean + 0.1f * smooth;
    }
}

extern "C" void kernel_launch(void* const* d_in, const int* in_sizes, int n_in,
                              void* d_out, int out_size)
{
    const float* lp      = (const float*)d_in[0];
    const int*   targets = (const int*)d_in[1];
    const int*   in_len  = (const int*)d_in[2];
    const int*   tgt_len = (const int*)d_in[3];
    float*       out     = (float*)d_out;

    fused_ctc_entropy<<<B_DIM + N_ENT_BLOCKS, THREADS>>>(lp, targets, in_len, tgt_len);
    finalize_kernel<<<1, 256>>>(out);
}

// round 4
// speedup vs baseline: 3.8122x; 2.7118x over previous
#include <cuda_runtime.h>
#include <cuda_bf16.h>

// Problem constants
#define T_DIM 1024
#define B_DIM 128
#define C_DIM 256
#define L_DIM 64
#define S_DIM 129           // 2*L+1
#define BC    (B_DIM * C_DIM)
#define NEGV  (-1e30f)

#define DGRP  8             // cp.async pipeline depth (groups in flight)
#define NSLOT 10            // smem ring slots = DGRP + 2 (2 barriers of slack)
#define N_ENT_BLOCKS 1024
#define THREADS 256

// Deterministic two-stage reduction scratch (fully overwritten every call)
__device__ float g_ent_part[N_ENT_BLOCKS];
__device__ float g_ctc_part[B_DIM];

#define CP_ASYNC_4(dst_smem_u32, src_gptr) \
    asm volatile("cp.async.ca.shared.global [%0], [%1], 4;" :: "r"(dst_smem_u32), "l"(src_gptr))
#define CP_ASYNC_COMMIT() asm volatile("cp.async.commit_group;")
#define CP_ASYNC_WAIT(n)  asm volatile("cp.async.wait_group %0;" :: "n"(n))

__global__ void __launch_bounds__(THREADS)
fused_ctc_entropy(const float* __restrict__ lp,
                  const int* __restrict__ targets,
                  const int* __restrict__ in_len,
                  const int* __restrict__ tgt_len)
{
    const int tid = threadIdx.x;

    __shared__ float rows[NSLOT][C_DIM];   // staged log_prob rows (10 KB)
    __shared__ float buf[2][S_DIM + 2];    // [pad2 | states], double buffered
    __shared__ float cap[2];
    __shared__ float red[THREADS / 32];

    if (blockIdx.x < B_DIM) {
        // ================= CTC DP block: one batch element =================
        const int b = blockIdx.x;
        const int s = tid;                   // state index; active for s < S_DIM

        if (tid < 2) { buf[0][tid] = NEGV; buf[1][tid] = NEGV; }

        int  label  = 0;
        bool allow2 = false;
        if (s < S_DIM && (s & 1)) {
            label  = targets[b * L_DIM + (s >> 1)];
            allow2 = (s == 1) || (label != targets[b * L_DIM + (s >> 1) - 1]);
        }

        const int Tlen = in_len[b];          // in [T/2, T]
        const int tl   = tgt_len[b];
        const float* rowbase = lp + b * C_DIM;    // row t at rowbase + t*BC

        // t = 0 init (direct gather, one-time)
        float a = NEGV;
        if (s <= 1) a = rowbase[label];

        // Prime the pipeline: rows 1..DGRP, one commit group per row
        #pragma unroll
        for (int r = 1; r <= DGRP; ++r) {
            unsigned dst = (unsigned)__cvta_generic_to_shared(&rows[r % NSLOT][tid]);
            CP_ASYNC_4(dst, rowbase + r * BC + tid);
            CP_ASYNC_COMMIT();
        }

        __syncthreads();   // pads visible

        int p = 0;
        for (int t = 1; t < Tlen; ++t) {
            if (s < S_DIM) buf[p][2 + s] = a;
            CP_ASYNC_WAIT(DGRP - 1);         // row t has landed
            __syncthreads();

            // issue row t+DGRP into its slot (slot last read 2 barriers ago)
            {
                int tpre = t + DGRP;
                if (tpre > T_DIM - 1) tpre = T_DIM - 1;
                unsigned dst = (unsigned)__cvta_generic_to_shared(
                    &rows[(t + DGRP) % NSLOT][tid]);
                CP_ASYNC_4(dst, rowbase + tpre * BC + tid);
                CP_ASYNC_COMMIT();
            }

            if (s < S_DIM) {
                float curlp = rows[t % NSLOT][label];
                float p1 = buf[p][1 + s];
                float p2 = allow2 ? buf[p][s] : NEGV;
                float m  = fmaxf(a, fmaxf(p1, p2));
                a = m + __logf(__expf(a - m) + __expf(p1 - m) + __expf(p2 - m)) + curlp;
            }
            p ^= 1;
        }
        CP_ASYNC_WAIT(0);                    // drain before exit

        // a holds alpha at t = Tlen-1; capture end states
        if (s == 2 * tl)     cap[0] = a;
        if (s == 2 * tl - 1) cap[1] = a;
        __syncthreads();

        if (s == 0) {
            float a1 = cap[0], a0 = cap[1];
            float m  = fmaxf(a1, a0);
            float ll = m + __logf(__expf(a1 - m) + __expf(a0 - m));
            float nll = -ll;
            g_ctc_part[b] = (nll > 1e29f) ? 0.0f : nll;   // zero_infinity
        }
    } else {
        // ================= Entropy block: sum exp(lp)*lp =================
        const int eb = blockIdx.x - B_DIM;
        const float4* v = (const float4*)lp;
        const int n4 = (T_DIM * B_DIM * C_DIM) / 4;

        float acc = 0.0f;
        for (int i = eb * THREADS + tid; i < n4; i += N_ENT_BLOCKS * THREADS) {
            float4 x = v[i];
            acc += __expf(x.x) * x.x;
            acc += __expf(x.y) * x.y;
            acc += __expf(x.z) * x.z;
            acc += __expf(x.w) * x.w;
        }

        #pragma unroll
        for (int o = 16; o > 0; o >>= 1)
            acc += __shfl_down_sync(0xFFFFFFFFu, acc, o);
        if ((tid & 31) == 0) red[tid >> 5] = acc;
        __syncthreads();
        if (tid < THREADS / 32) {
            float r = red[tid];
            #pragma unroll
            for (int o = (THREADS / 64); o > 0; o >>= 1)
                r += __shfl_down_sync(0xFFFFFFFFu, r, o);
            if (tid == 0) g_ent_part[eb] = r;
        }
    }
}

__global__ void __launch_bounds__(256)
finalize_kernel(float* __restrict__ out)
{
    const int tid = threadIdx.x;
    float acc = 0.0f;
    for (int i = tid; i < N_ENT_BLOCKS; i += 256) acc += g_ent_part[i];

    float c = (tid < B_DIM) ? g_ctc_part[tid] : 0.0f;

    __shared__ float red[8], redc[8];
    #pragma unroll
    for (int o = 16; o > 0; o >>= 1) {
        acc += __shfl_down_sync(0xFFFFFFFFu, acc, o);
        c   += __shfl_down_sync(0xFFFFFFFFu, c, o);
    }
    if ((tid & 31) == 0) { red[tid >> 5] = acc; redc[tid >> 5] = c; }
    __syncthreads();
    if (tid == 0) {
        float es = 0.0f, cs = 0.0f;
        #pragma unroll
        for (int i = 0; i < 8; ++i) { es += red[i]; cs += redc[i]; }
        float smooth   = es / (float)(T_DIM * B_DIM);
        float ctc_mean = cs / (float)B_DIM;
        out[0] = 0.9f * ctc_mean + 0.1f * smooth;
    }
}

extern "C" void kernel_launch(void* const* d_in, const int* in_sizes, int n_in,
                              void* d_out, int out_size)
{
    const float* lp      = (const float*)d_in[0];
    const int*   targets = (const int*)d_in[1];
    const int*   in_len  = (const int*)d_in[2];
    const int*   tgt_len = (const int*)d_in[3];
    float*       out     = (float*)d_out;

    fused_ctc_entropy<<<B_DIM + N_ENT_BLOCKS, THREADS>>>(lp, targets, in_len, tgt_len);
    finalize_kernel<<<1, 256>>>(out);
}